// round 1
// baseline (speedup 1.0000x reference)
#include <cuda_runtime.h>
#include <cuda_bf16.h>
#include <math.h>
#include <stdint.h>

// Problem constants
#define NN   12000      // nodes
#define NE   120000     // edges
#define FF   768        // feature width
#define PLD  4608       // node-projection row width (6 heads x 768)

// ---------------- scratch (device globals; no allocation allowed) ------------
__device__ __nv_bfloat16 g_e1[(size_t)NE * FF];   // edge features (conv1 input)
__device__ __nv_bfloat16 g_e2[(size_t)NE * FF];   // edge features (conv2 input)
__device__ __nv_bfloat16 g_Sf[(size_t)NE * FF];   // sigmoid(f-head) staging
__device__ __nv_bfloat16 g_P [(size_t)NN * PLD];  // node projections
__device__ float         g_x [(size_t)NN * FF];   // running node features (x -> x1 -> x2)
__device__ float         g_pool[FF];              // global sum pool

// ---------------- PTX helpers ------------------------------------------------
__device__ __forceinline__ uint32_t smem_u32(const void* p) {
    return (uint32_t)__cvta_generic_to_shared(p);
}

__device__ __forceinline__ void ldsm4(uint32_t* r, uint32_t addr) {
    asm volatile("ldmatrix.sync.aligned.m8n8.x4.shared.b16 {%0,%1,%2,%3},[%4];"
                 : "=r"(r[0]), "=r"(r[1]), "=r"(r[2]), "=r"(r[3]) : "r"(addr));
}
__device__ __forceinline__ void ldsm4t(uint32_t* r, uint32_t addr) {
    asm volatile("ldmatrix.sync.aligned.m8n8.x4.trans.shared.b16 {%0,%1,%2,%3},[%4];"
                 : "=r"(r[0]), "=r"(r[1]), "=r"(r[2]), "=r"(r[3]) : "r"(addr));
}
__device__ __forceinline__ void mma16816(float* c, const uint32_t* a, uint32_t b0, uint32_t b1) {
    asm volatile(
        "mma.sync.aligned.m16n8k16.row.col.f32.bf16.bf16.f32 "
        "{%0,%1,%2,%3},{%4,%5,%6,%7},{%8,%9},{%0,%1,%2,%3};"
        : "+f"(c[0]), "+f"(c[1]), "+f"(c[2]), "+f"(c[3])
        : "r"(a[0]), "r"(a[1]), "r"(a[2]), "r"(a[3]), "r"(b0), "r"(b1));
}

// ---------------- fused GEMM -------------------------------------------------
// C[M,768] = A[M,K] @ B[K,768]  (bf16 inputs, fp32 accum), epilogue variants.
enum { EPI_STORE = 0, EPI_TANH = 1, EPI_SIGF = 2, EPI_MSGS = 3, EPI_GATE = 4 };

struct GemmArgs {
    const void*          A;      // bf16 (ABF) or fp32
    int                  lda;
    int                  M;
    int                  K;
    const float*         B;      // fp32 weights (already offset to slice start), row stride ldb
    int                  ldb;
    const float*         bias;   // [768] or null
    const __nv_bfloat16* Pd;     // node projection slice for dst (ld PLD)
    const __nv_bfloat16* Ps;     // node projection slice for src (ld PLD)
    const int*           dst;
    const int*           src;
    const __nv_bfloat16* aux;    // Sf (MSGS) or e_in (GATE), ld 768
    __nv_bfloat16*       outb;   // bf16 output
    int                  ldo;
    float*               atom;   // fp32 atomic target (MSGS), ld 768
};

template<int EPI, bool ABF>
__global__ __launch_bounds__(256, 2) void gemm_k(GemmArgs g) {
    __shared__ alignas(16) __nv_bfloat16 As[128][40];   // 128x32 tile, +8 pad
    __shared__ alignas(16) __nv_bfloat16 Bs[32][136];   // 32x128 tile, +8 pad

    const int tid  = threadIdx.x;
    const int lane = tid & 31;
    const int warp = tid >> 5;
    const int bm   = blockIdx.x * 128;
    const int bn   = blockIdx.y * 128;
    const int wm   = (warp & 1) * 64;    // warp grid 2 (M) x 4 (N)
    const int wn   = (warp >> 1) * 32;

    float acc[4][4][4];
    #pragma unroll
    for (int i = 0; i < 4; i++)
        #pragma unroll
        for (int j = 0; j < 4; j++)
            #pragma unroll
            for (int k = 0; k < 4; k++) acc[i][j][k] = 0.f;

    for (int k0 = 0; k0 < g.K; k0 += 32) {
        __syncthreads();
        // ---- load A tile (128 x 32) ----
        if (ABF) {
            const __nv_bfloat16* A = (const __nv_bfloat16*)g.A;
            int r  = tid >> 2;
            int cc = (tid & 3) * 8;
            #pragma unroll
            for (int rr = 0; rr < 128; rr += 64) {
                int row  = r + rr;
                int grow = bm + row;
                uint4 v = make_uint4(0u, 0u, 0u, 0u);
                if (grow < g.M) v = *(const uint4*)(A + (size_t)grow * g.lda + k0 + cc);
                *(uint4*)&As[row][cc] = v;
            }
        } else {
            const float* A = (const float*)g.A;
            int r  = tid >> 3;
            int cc = (tid & 7) * 4;
            #pragma unroll
            for (int rr = 0; rr < 128; rr += 32) {
                int row  = r + rr;
                int grow = bm + row;
                float4 v = make_float4(0.f, 0.f, 0.f, 0.f);
                if (grow < g.M) v = *(const float4*)(A + (size_t)grow * g.lda + k0 + cc);
                *(__nv_bfloat162*)&As[row][cc]     = __floats2bfloat162_rn(v.x, v.y);
                *(__nv_bfloat162*)&As[row][cc + 2] = __floats2bfloat162_rn(v.z, v.w);
            }
        }
        // ---- load B tile (32 x 128), fp32 -> bf16 ----
        {
            int r  = tid >> 5;
            int cc = (lane) * 4;
            #pragma unroll
            for (int rr = 0; rr < 32; rr += 8) {
                int row = r + rr;
                float4 v = *(const float4*)(g.B + (size_t)(k0 + row) * g.ldb + bn + cc);
                *(__nv_bfloat162*)&Bs[row][cc]     = __floats2bfloat162_rn(v.x, v.y);
                *(__nv_bfloat162*)&Bs[row][cc + 2] = __floats2bfloat162_rn(v.z, v.w);
            }
        }
        __syncthreads();

        // ---- compute: 2 k-steps of 16 ----
        #pragma unroll
        for (int ks = 0; ks < 2; ks++) {
            uint32_t a[4][4], b[2][4];
            #pragma unroll
            for (int mi = 0; mi < 4; mi++) {
                uint32_t addr = smem_u32(&As[wm + mi * 16 + (lane & 15)][ks * 16 + (lane >> 4) * 8]);
                ldsm4(a[mi], addr);
            }
            #pragma unroll
            for (int np = 0; np < 2; np++) {
                uint32_t addr = smem_u32(&Bs[ks * 16 + (lane & 15)][wn + np * 16 + (lane >> 4) * 8]);
                ldsm4t(b[np], addr);
            }
            #pragma unroll
            for (int mi = 0; mi < 4; mi++)
                #pragma unroll
                for (int ni = 0; ni < 4; ni++)
                    mma16816(acc[mi][ni], a[mi], b[ni >> 1][(ni & 1) * 2], b[ni >> 1][(ni & 1) * 2 + 1]);
        }
    }

    // ---- epilogue ----
    const int tig = lane & 3;
    const int gid = lane >> 2;
    #pragma unroll
    for (int mi = 0; mi < 4; mi++) {
        #pragma unroll
        for (int h = 0; h < 2; h++) {
            int rr = bm + wm + mi * 16 + gid + h * 8;
            if (rr >= g.M) continue;
            int d = 0, s = 0;
            if (EPI == EPI_SIGF || EPI == EPI_MSGS || EPI == EPI_GATE) {
                d = g.dst[rr];
                s = g.src[rr];
            }
            #pragma unroll
            for (int ni = 0; ni < 4; ni++) {
                #pragma unroll
                for (int cc = 0; cc < 2; cc++) {
                    int   c = bn + wn + ni * 8 + tig * 2 + cc;
                    float v = acc[mi][ni][h * 2 + cc];
                    if (EPI == EPI_STORE) {
                        g.outb[(size_t)rr * g.ldo + c] = __float2bfloat16(v);
                    } else if (EPI == EPI_TANH) {
                        g.outb[(size_t)rr * g.ldo + c] = __float2bfloat16(tanhf(v + g.bias[c]));
                    } else {
                        float t = v + __bfloat162float(g.Pd[(size_t)d * PLD + c])
                                    + __bfloat162float(g.Ps[(size_t)s * PLD + c]) + g.bias[c];
                        if (EPI == EPI_SIGF) {
                            g.outb[(size_t)rr * 768 + c] = __float2bfloat16(1.f / (1.f + __expf(-t)));
                        } else if (EPI == EPI_MSGS) {
                            float m = fmaxf(t, 0.f) * __bfloat162float(g.aux[(size_t)rr * 768 + c]);
                            atomicAdd(&g.atom[(size_t)d * 768 + c], m);
                        } else { // EPI_GATE
                            float gt = 1.f / (1.f + __expf(-t));
                            g.outb[(size_t)rr * 768 + c] = __float2bfloat16(
                                __bfloat162float(g.aux[(size_t)rr * 768 + c]) * (1.f + gt));
                        }
                    }
                }
            }
        }
    }
}

// ---------------- small kernels ---------------------------------------------
__global__ void copy_x_kernel(const float* __restrict__ x) {
    int i = blockIdx.x * blockDim.x + threadIdx.x;
    const int n4 = NN * FF / 4;
    if (i < n4) ((float4*)g_x)[i] = ((const float4*)x)[i];
    if (i < FF) g_pool[i] = 0.f;
}

__global__ void pool_kernel() {
    int c  = blockIdx.x * blockDim.x + threadIdx.x;  // 0..767
    int r0 = blockIdx.y * 240;
    int r1 = min(r0 + 240, NN);
    float s = 0.f;
    for (int r = r0; r < r1; r++) s += g_x[(size_t)r * FF + c];
    atomicAdd(&g_pool[c], s);
}

__global__ void final_kernel(const float* __restrict__ Wd, const float* __restrict__ bd,
                             float* __restrict__ out) {
    int l = threadIdx.x;  // one warp; lanes 0..15 active
    float logit = -1e30f;
    if (l < 16) {
        float s = bd[l];
        #pragma unroll 8
        for (int f = 0; f < FF; f++) s += g_pool[f] * Wd[f * 16 + l];
        logit = s;
    }
    float m = logit;
    #pragma unroll
    for (int o = 16; o > 0; o >>= 1) m = fmaxf(m, __shfl_xor_sync(0xffffffffu, m, o));
    float e = (l < 16) ? __expf(logit - m) : 0.f;
    float sum = e;
    #pragma unroll
    for (int o = 16; o > 0; o >>= 1) sum += __shfl_xor_sync(0xffffffffu, sum, o);
    if (l < 16) out[l] = e / sum;
}

// ---------------- host orchestration ----------------------------------------
extern "C" void kernel_launch(void* const* d_in, const int* in_sizes, int n_in,
                              void* d_out, int out_size) {
    (void)in_sizes; (void)n_in; (void)out_size;
    const float* x     = (const float*)d_in[0];
    const float* e_raw = (const float*)d_in[1];
    const int*   src   = (const int*)d_in[2];
    const int*   dst   = (const int*)d_in[3];
    const float* W_pre = (const float*)d_in[4];
    const float* b_pre = (const float*)d_in[5];
    const float* Wf1 = (const float*)d_in[6],  *bf1 = (const float*)d_in[7];
    const float* Ws1 = (const float*)d_in[8],  *bs1 = (const float*)d_in[9];
    const float* We1 = (const float*)d_in[10], *be1 = (const float*)d_in[11];
    const float* Wf2 = (const float*)d_in[12], *bf2 = (const float*)d_in[13];
    const float* Ws2 = (const float*)d_in[14], *bs2 = (const float*)d_in[15];
    const float* Wd  = (const float*)d_in[18], *bd  = (const float*)d_in[19];

    void *pe1v, *pe2v, *pSfv, *pPv, *pxv;
    cudaGetSymbolAddress(&pe1v, g_e1);
    cudaGetSymbolAddress(&pe2v, g_e2);
    cudaGetSymbolAddress(&pSfv, g_Sf);
    cudaGetSymbolAddress(&pPv,  g_P);
    cudaGetSymbolAddress(&pxv,  g_x);
    __nv_bfloat16* pe1 = (__nv_bfloat16*)pe1v;
    __nv_bfloat16* pe2 = (__nv_bfloat16*)pe2v;
    __nv_bfloat16* pSf = (__nv_bfloat16*)pSfv;
    __nv_bfloat16* pP  = (__nv_bfloat16*)pPv;
    float*         px  = (float*)pxv;

    const dim3 blk(256);
    const dim3 gE((NE + 127) / 128, 6);
    const dim3 gN((NN + 127) / 128, 6);
    const int  W2 = 768 * 768;   // weight block offset (768 rows)

    // 1. g_x = x  (and zero g_pool)
    copy_x_kernel<<<(NN * FF / 4 + 255) / 256, blk>>>(x);

    // 2. pre-edge: e1 = tanh(e_raw @ W_pre + b_pre)
    {
        GemmArgs a = {};
        a.A = e_raw; a.lda = 64; a.M = NE; a.K = 64;
        a.B = W_pre; a.ldb = 768; a.bias = b_pre;
        a.outb = pe1; a.ldo = 768;
        gemm_k<EPI_TANH, false><<<gE, blk>>>(a);
    }

    // helper lambdas ------------------------------------------------------
    auto node_pass = [&](const float* Wblk, int coloff) {
        GemmArgs a = {};
        a.A = px; a.lda = 768; a.M = NN; a.K = 768;
        a.B = Wblk; a.ldb = 768;
        a.outb = pP + coloff; a.ldo = PLD;
        gemm_k<EPI_STORE, false><<<gN, blk>>>(a);
    };
    auto edge_pass = [&](int epi, const __nv_bfloat16* eIn, const float* Wblk,
                         const float* bias, int pdOff, int psOff,
                         const __nv_bfloat16* aux, __nv_bfloat16* outb) {
        GemmArgs a = {};
        a.A = eIn; a.lda = 768; a.M = NE; a.K = 768;
        a.B = Wblk + (size_t)1536 * 768; a.ldb = 768;
        a.bias = bias;
        a.Pd = pP + pdOff; a.Ps = pP + psOff;
        a.dst = dst; a.src = src;
        a.aux = aux; a.outb = outb; a.ldo = 768; a.atom = px;
        if (epi == EPI_SIGF)      gemm_k<EPI_SIGF, true><<<gE, blk>>>(a);
        else if (epi == EPI_MSGS) gemm_k<EPI_MSGS, true><<<gE, blk>>>(a);
        else                      gemm_k<EPI_GATE, true><<<gE, blk>>>(a);
    };

    // 3. conv1 node projections (P cols: 0 Pd_f, 768 Ps_f, 1536 Pd_s, 2304 Ps_s, 3072 Pd_e, 3840 Ps_e)
    node_pass(Wf1,      0);
    node_pass(Wf1 + W2, 768);
    node_pass(Ws1,      1536);
    node_pass(Ws1 + W2, 2304);
    node_pass(We1,      3072);
    node_pass(We1 + W2, 3840);

    // 4. conv1 edge passes
    edge_pass(EPI_SIGF, pe1, Wf1, bf1, 0,    768,  nullptr, pSf);  // Sf = sigmoid(f)
    edge_pass(EPI_GATE, pe1, We1, be1, 3072, 3840, pe1,     pe2);  // e2 = e1*(1+sigmoid(g))
    edge_pass(EPI_MSGS, pe1, Ws1, bs1, 1536, 2304, pSf,     nullptr); // x += scatter(relu(s)*Sf)

    // 5. conv2 node projections (from x1 = g_x)
    node_pass(Wf2,      0);
    node_pass(Wf2 + W2, 768);
    node_pass(Ws2,      1536);
    node_pass(Ws2 + W2, 2304);

    // 6. conv2 edge passes (gate head g2 is unused in the reference -> skipped)
    edge_pass(EPI_SIGF, pe2, Wf2, bf2, 0,    768,  nullptr, pSf);
    edge_pass(EPI_MSGS, pe2, Ws2, bs2, 1536, 2304, pSf,     nullptr);

    // 7. pool + dense + softmax
    pool_kernel<<<dim3(3, 50), blk>>>();
    final_kernel<<<1, 32>>>(Wd, bd, (float*)d_out);
}

// round 3
// speedup vs baseline: 1.4751x; 1.4751x over previous
#include <cuda_runtime.h>
#include <cuda_bf16.h>
#include <math.h>
#include <stdint.h>

// Problem constants
#define NN   12000      // nodes
#define NE   120000     // edges
#define FF   768        // feature width
#define PLD  4608       // node-projection row width (6 heads x 768)
#define SLOT ((size_t)FF * FF)   // elems per weight slot [768][768]

// ---------------- scratch (device globals; no allocation allowed) ------------
__device__ __nv_bfloat16 g_e1[(size_t)NE * FF];     // edge features (conv1 input)
__device__ __nv_bfloat16 g_e2[(size_t)NE * FF];     // edge features (conv2 input)
__device__ __nv_bfloat16 g_Sf[(size_t)NE * FF];     // sigmoid(f-head) staging
__device__ __nv_bfloat16 g_P [(size_t)NN * PLD];    // node projections (6 heads)
__device__ float         g_x [(size_t)NN * FF];     // running node features (fp32)
__device__ __nv_bfloat16 g_xb[(size_t)NN * FF];     // bf16 copy of node features
__device__ __nv_bfloat16 g_erb[(size_t)NE * 64];    // bf16 e_raw
__device__ __nv_bfloat16 g_Wt[(size_t)16 * SLOT];   // 16 bf16 weight slots [K][768]
__device__ float         g_pool[FF];

// ---------------- PTX helpers ------------------------------------------------
__device__ __forceinline__ uint32_t s2u(const void* p) {
    return (uint32_t)__cvta_generic_to_shared(p);
}
#define CPA16(dst, src, v) \
    asm volatile("cp.async.cg.shared.global [%0], [%1], 16, %2;" \
                 :: "r"(dst), "l"(src), "r"((v) ? 16 : 0))
#define CPA_COMMIT() asm volatile("cp.async.commit_group;" ::: "memory")
#define CPA_WAIT2()  asm volatile("cp.async.wait_group 2;" ::: "memory")
#define CPA_WAIT1()  asm volatile("cp.async.wait_group 1;" ::: "memory")
#define CPA_WAIT0()  asm volatile("cp.async.wait_group 0;" ::: "memory")

__device__ __forceinline__ void ldsm4(uint32_t* r, uint32_t addr) {
    asm volatile("ldmatrix.sync.aligned.m8n8.x4.shared.b16 {%0,%1,%2,%3},[%4];"
                 : "=r"(r[0]), "=r"(r[1]), "=r"(r[2]), "=r"(r[3]) : "r"(addr));
}
__device__ __forceinline__ void ldsm4t(uint32_t* r, uint32_t addr) {
    asm volatile("ldmatrix.sync.aligned.m8n8.x4.trans.shared.b16 {%0,%1,%2,%3},[%4];"
                 : "=r"(r[0]), "=r"(r[1]), "=r"(r[2]), "=r"(r[3]) : "r"(addr));
}
__device__ __forceinline__ void mma16816(float* c, const uint32_t* a, uint32_t b0, uint32_t b1) {
    asm volatile(
        "mma.sync.aligned.m16n8k16.row.col.f32.bf16.bf16.f32 "
        "{%0,%1,%2,%3},{%4,%5,%6,%7},{%8,%9},{%0,%1,%2,%3};"
        : "+f"(c[0]), "+f"(c[1]), "+f"(c[2]), "+f"(c[3])
        : "r"(a[0]), "r"(a[1]), "r"(a[2]), "r"(a[3]), "r"(b0), "r"(b1));
}
__device__ __forceinline__ uint32_t pk2(float a, float b) {
    __nv_bfloat162 h = __floats2bfloat162_rn(a, b);
    return *(uint32_t*)&h;
}
__device__ __forceinline__ float ubf(const __nv_bfloat16& v) { return __bfloat162float(v); }

// ---------------- fused pipelined mma.sync GEMM -------------------------------
// C[M,768-slice] = A[M,K] @ B[K,768]; smem: A tile 128x32 (stride 40h = 80B),
// B tile 32x128 (stride 136h = 272B). 4-stage cp.async pipeline.
enum { EPI_STORE = 0, EPI_TANH = 1, EPI_SIGF = 2, EPI_MSGS = 3, EPI_GATE = 4 };

#define A_TB  10240                    // 128*40*2
#define B_TB  8704                     // 32*136*2
#define SMEM_BYTES (4 * (A_TB + B_TB)) // 75776

struct GArgs {
    const __nv_bfloat16* A;    int lda; int M; int K;
    const __nv_bfloat16* B;    int ldb;                 // [K][768] bf16
    const float*         bias;
    const __nv_bfloat16* Pd;   const __nv_bfloat16* Ps; // ld PLD
    const int*           dst;  const int* srcI;
    const __nv_bfloat16* aux;  // ld 768
    __nv_bfloat16*       outb; int ldo;
    float*               atom; // ld 768
    int                  multi;    // node-pass: slots merged into grid.x
    int                  slotBase; // first slot index (0 conv1, 9 conv2)
};

template<int EPI>
__global__ void __launch_bounds__(256, 2) gemm_k(GArgs g) {
    extern __shared__ char smem_raw[];
    const uint32_t sb = s2u(smem_raw);

    const int tid = threadIdx.x, lane = tid & 31, warp = tid >> 5;
    const int bm = blockIdx.y * 128;

    // decode N-block (and weight slot for merged node passes)
    int bn, outCol;
    const __nv_bfloat16* Bp = g.B;
    if (EPI == EPI_STORE && g.multi) {
        int idx = blockIdx.x / 6, nb = blockIdx.x % 6;
        int slot = g.slotBase + (idx >> 1) * 3 + (idx & 1);
        Bp += (size_t)slot * SLOT;
        bn = nb * 128;
        outCol = idx * 768 + nb * 128;
    } else {
        bn = blockIdx.x * 128;
        outCol = bn;
    }

    // ---- loader mapping: 1024 chunks of 16B (A 512 + B 512), 256 thr x 4 ----
    const int ar0 = tid >> 2, akc = tid & 3;       // A rows tid>>2 and +64
    const int br0 = tid >> 4, bkc = tid & 15;      // B rows tid>>4 and +16
    const uint32_t adst0 = ar0 * 80 + akc * 16;
    const uint32_t adst1 = adst0 + 64 * 80;
    const uint32_t bdst0 = br0 * 272 + bkc * 16;
    const uint32_t bdst1 = bdst0 + 16 * 272;
    const bool av0 = (bm + ar0) < g.M;
    const bool av1 = (bm + ar0 + 64) < g.M;
    const __nv_bfloat16* asrc0 = g.A + (size_t)min(bm + ar0,      g.M - 1) * g.lda + akc * 8;
    const __nv_bfloat16* asrc1 = g.A + (size_t)min(bm + ar0 + 64, g.M - 1) * g.lda + akc * 8;
    const __nv_bfloat16* bsrc0 = Bp + (size_t)br0        * g.ldb + bn + bkc * 8;
    const __nv_bfloat16* bsrc1 = Bp + (size_t)(br0 + 16) * g.ldb + bn + bkc * 8;
    const size_t bstep = (size_t)32 * g.ldb;

    auto load_stage = [&](int buf) {
        const uint32_t Ab = sb + buf * A_TB;
        const uint32_t Bb = sb + 4 * A_TB + buf * B_TB;
        CPA16(Ab + adst0, asrc0, av0);
        CPA16(Ab + adst1, asrc1, av1);
        CPA16(Bb + bdst0, bsrc0, true);
        CPA16(Bb + bdst1, bsrc1, true);
        asrc0 += 32; asrc1 += 32; bsrc0 += bstep; bsrc1 += bstep;
        CPA_COMMIT();
    };

    const int S = g.K >> 5;       // stages of K=32
    const int wm = (warp & 1) * 64;
    const int wn = (warp >> 1) * 32;

    float acc[4][4][4];
    #pragma unroll
    for (int i = 0; i < 4; i++)
        #pragma unroll
        for (int j = 0; j < 4; j++)
            #pragma unroll
            for (int k = 0; k < 4; k++) acc[i][j][k] = 0.f;

    // prologue: fill up to 3 stages
    const int pre = S < 3 ? S : 3;
    for (int p = 0; p < pre; p++) load_stage(p);

    for (int s = 0; s < S; s++) {
        const int rem = S - s - 1;
        if (rem >= 2)      CPA_WAIT2();
        else if (rem == 1) CPA_WAIT1();
        else               CPA_WAIT0();
        __syncthreads();
        if (s + 3 < S) load_stage((s + 3) & 3);

        const uint32_t Ab = sb + (s & 3) * A_TB;
        const uint32_t Bb = sb + 4 * A_TB + (s & 3) * B_TB;
        #pragma unroll
        for (int ks = 0; ks < 2; ks++) {
            uint32_t a[4][4], b[2][4];
            #pragma unroll
            for (int mi = 0; mi < 4; mi++)
                ldsm4(a[mi], Ab + ((wm + mi * 16 + (lane & 15)) * 40 + ks * 16 + (lane >> 4) * 8) * 2);
            #pragma unroll
            for (int np = 0; np < 2; np++)
                ldsm4t(b[np], Bb + ((ks * 16 + (lane & 15)) * 136 + wn + np * 16 + (lane >> 4) * 8) * 2);
            #pragma unroll
            for (int mi = 0; mi < 4; mi++)
                #pragma unroll
                for (int ni = 0; ni < 4; ni++)
                    mma16816(acc[mi][ni], a[mi], b[ni >> 1][(ni & 1) * 2], b[ni >> 1][(ni & 1) * 2 + 1]);
        }
        __syncthreads();
    }

    // ------------------------------ epilogue ------------------------------
    const int tig = lane & 3;
    const int gid = lane >> 2;
    #pragma unroll
    for (int mi = 0; mi < 4; mi++) {
        #pragma unroll
        for (int h = 0; h < 2; h++) {
            const int rr = bm + wm + mi * 16 + gid + h * 8;
            if (rr >= g.M) continue;
            int di = 0, si = 0;
            if (EPI == EPI_SIGF || EPI == EPI_MSGS || EPI == EPI_GATE) {
                di = g.dst[rr]; si = g.srcI[rr];
            }
            #pragma unroll
            for (int ni = 0; ni < 4; ni++) {
                const int cl = wn + ni * 8 + tig * 2;       // col within 768-slice
                const float v0 = acc[mi][ni][h * 2];
                const float v1 = acc[mi][ni][h * 2 + 1];
                if (EPI == EPI_STORE) {
                    *(uint32_t*)(g.outb + (size_t)rr * g.ldo + outCol + cl) = pk2(v0, v1);
                } else if (EPI == EPI_TANH) {
                    const int c = bn + cl;
                    float t0 = tanhf(v0 + g.bias[c]);
                    float t1 = tanhf(v1 + g.bias[c + 1]);
                    *(uint32_t*)(g.outb + (size_t)rr * g.ldo + c) = pk2(t0, t1);
                } else {
                    const int c = bn + cl;
                    float t0 = v0 + ubf(g.Pd[(size_t)di * PLD + c])
                                  + ubf(g.Ps[(size_t)si * PLD + c]) + g.bias[c];
                    float t1 = v1 + ubf(g.Pd[(size_t)di * PLD + c + 1])
                                  + ubf(g.Ps[(size_t)si * PLD + c + 1]) + g.bias[c + 1];
                    if (EPI == EPI_SIGF) {
                        *(uint32_t*)(g.outb + (size_t)rr * 768 + c) =
                            pk2(1.f / (1.f + __expf(-t0)), 1.f / (1.f + __expf(-t1)));
                    } else if (EPI == EPI_GATE) {
                        float a0 = ubf(g.aux[(size_t)rr * 768 + c]);
                        float a1 = ubf(g.aux[(size_t)rr * 768 + c + 1]);
                        *(uint32_t*)(g.outb + (size_t)rr * 768 + c) =
                            pk2(a0 * (1.f + 1.f / (1.f + __expf(-t0))),
                                a1 * (1.f + 1.f / (1.f + __expf(-t1))));
                    } else { // EPI_MSGS
                        float a0 = ubf(g.aux[(size_t)rr * 768 + c]);
                        float a1 = ubf(g.aux[(size_t)rr * 768 + c + 1]);
                        float m0 = fmaxf(t0, 0.f) * a0;
                        float m1 = fmaxf(t1, 0.f) * a1;
                        atomicAdd((float2*)(g.atom + (size_t)di * 768 + c), make_float2(m0, m1));
                    }
                }
            }
        }
    }
}

// ---------------- small kernels ----------------------------------------------
__global__ void copy_x_kernel(const float* __restrict__ x) {
    int i = blockIdx.x * blockDim.x + threadIdx.x;
    const int n4 = NN * FF / 4;
    if (i < n4) ((float4*)g_x)[i] = ((const float4*)x)[i];
    if (i < FF) g_pool[i] = 0.f;
}
__global__ void cvt_bf16_kernel(const float* __restrict__ s, __nv_bfloat16* __restrict__ d, int n4) {
    int i = blockIdx.x * blockDim.x + threadIdx.x;
    if (i < n4) {
        float4 v = ((const float4*)s)[i];
        ((__nv_bfloat162*)d)[i * 2]     = __floats2bfloat162_rn(v.x, v.y);
        ((__nv_bfloat162*)d)[i * 2 + 1] = __floats2bfloat162_rn(v.z, v.w);
    }
}
__global__ void pool_kernel() {
    int c  = blockIdx.x * blockDim.x + threadIdx.x;
    int r0 = blockIdx.y * 240;
    int r1 = min(r0 + 240, NN);
    float s = 0.f;
    for (int r = r0; r < r1; r++) s += g_x[(size_t)r * FF + c];
    atomicAdd(&g_pool[c], s);
}
__global__ void final_kernel(const float* __restrict__ Wd, const float* __restrict__ bd,
                             float* __restrict__ out) {
    int l = threadIdx.x;
    float logit = -1e30f;
    if (l < 16) {
        float s = bd[l];
        #pragma unroll 8
        for (int f = 0; f < FF; f++) s += g_pool[f] * Wd[f * 16 + l];
        logit = s;
    }
    float m = logit;
    #pragma unroll
    for (int o = 16; o > 0; o >>= 1) m = fmaxf(m, __shfl_xor_sync(0xffffffffu, m, o));
    float e = (l < 16) ? __expf(logit - m) : 0.f;
    float sum = e;
    #pragma unroll
    for (int o = 16; o > 0; o >>= 1) sum += __shfl_xor_sync(0xffffffffu, sum, o);
    if (l < 16) out[l] = e / sum;
}

// ---------------- host orchestration ------------------------------------------
extern "C" void kernel_launch(void* const* d_in, const int* in_sizes, int n_in,
                              void* d_out, int out_size) {
    (void)in_sizes; (void)n_in; (void)out_size;
    const float* x     = (const float*)d_in[0];
    const float* e_raw = (const float*)d_in[1];
    const int*   src   = (const int*)d_in[2];
    const int*   dst   = (const int*)d_in[3];
    const float* W_pre = (const float*)d_in[4];
    const float* b_pre = (const float*)d_in[5];
    const float* Wf1 = (const float*)d_in[6],  *bf1 = (const float*)d_in[7];
    const float* Ws1 = (const float*)d_in[8],  *bs1 = (const float*)d_in[9];
    const float* We1 = (const float*)d_in[10], *be1 = (const float*)d_in[11];
    const float* Wf2 = (const float*)d_in[12], *bf2 = (const float*)d_in[13];
    const float* Ws2 = (const float*)d_in[14], *bs2 = (const float*)d_in[15];
    const float* Wd  = (const float*)d_in[18], *bd  = (const float*)d_in[19];

    void *pe1v, *pe2v, *pSfv, *pPv, *pxv, *pxbv, *perbv, *pWtv;
    cudaGetSymbolAddress(&pe1v,  g_e1);
    cudaGetSymbolAddress(&pe2v,  g_e2);
    cudaGetSymbolAddress(&pSfv,  g_Sf);
    cudaGetSymbolAddress(&pPv,   g_P);
    cudaGetSymbolAddress(&pxv,   g_x);
    cudaGetSymbolAddress(&pxbv,  g_xb);
    cudaGetSymbolAddress(&perbv, g_erb);
    cudaGetSymbolAddress(&pWtv,  g_Wt);
    __nv_bfloat16* pe1  = (__nv_bfloat16*)pe1v;
    __nv_bfloat16* pe2  = (__nv_bfloat16*)pe2v;
    __nv_bfloat16* pSf  = (__nv_bfloat16*)pSfv;
    __nv_bfloat16* pP   = (__nv_bfloat16*)pPv;
    float*         px   = (float*)pxv;
    __nv_bfloat16* pxb  = (__nv_bfloat16*)pxbv;
    __nv_bfloat16* perb = (__nv_bfloat16*)perbv;
    __nv_bfloat16* pWt  = (__nv_bfloat16*)pWtv;

    cudaFuncSetAttribute(gemm_k<EPI_STORE>, cudaFuncAttributeMaxDynamicSharedMemorySize, SMEM_BYTES);
    cudaFuncSetAttribute(gemm_k<EPI_TANH>,  cudaFuncAttributeMaxDynamicSharedMemorySize, SMEM_BYTES);
    cudaFuncSetAttribute(gemm_k<EPI_SIGF>,  cudaFuncAttributeMaxDynamicSharedMemorySize, SMEM_BYTES);
    cudaFuncSetAttribute(gemm_k<EPI_MSGS>,  cudaFuncAttributeMaxDynamicSharedMemorySize, SMEM_BYTES);
    cudaFuncSetAttribute(gemm_k<EPI_GATE>,  cudaFuncAttributeMaxDynamicSharedMemorySize, SMEM_BYTES);

    const dim3 blk(256);
    const dim3 gE(6, (NE + 127) / 128);   // x = N-block fastest -> A tile L2-shared
    const dim3 gN1(36, (NN + 127) / 128); // 6 slots x 6 N-blocks
    const dim3 gN2(24, (NN + 127) / 128); // 4 slots x 6 N-blocks

    // 1. fp32 state copy + bf16 conversions (inputs + all weights; no transpose)
    copy_x_kernel<<<(NN * FF / 4 + 255) / 256, blk>>>(x);
    cvt_bf16_kernel<<<(NN * FF / 4 + 255) / 256, blk>>>(x, pxb, NN * FF / 4);
    cvt_bf16_kernel<<<(NE * 64 / 4 + 255) / 256, blk>>>(e_raw, perb, NE * 64 / 4);
    {
        const int n4w = (int)(3 * SLOT / 4);  // one weight matrix = 3 slots
        const int gw  = (n4w + 255) / 256;
        cvt_bf16_kernel<<<gw, blk>>>(Wf1, pWt,             n4w);   // slots 0-2
        cvt_bf16_kernel<<<gw, blk>>>(Ws1, pWt + 3 * SLOT,  n4w);   // slots 3-5
        cvt_bf16_kernel<<<gw, blk>>>(We1, pWt + 6 * SLOT,  n4w);   // slots 6-8
        cvt_bf16_kernel<<<gw, blk>>>(Wf2, pWt + 9 * SLOT,  n4w);   // slots 9-11
        cvt_bf16_kernel<<<gw, blk>>>(Ws2, pWt + 12 * SLOT, n4w);   // slots 12-14
        const int n4p = 64 * FF / 4;
        cvt_bf16_kernel<<<(n4p + 255) / 256, blk>>>(W_pre, pWt + 15 * SLOT, n4p); // slot 15
    }
    auto slot = [&](int i) { return pWt + (size_t)i * SLOT; };

    // 2. pre-edge: e1 = tanh(e_raw @ W_pre + b_pre)
    {
        GArgs a = {};
        a.A = perb; a.lda = 64; a.M = NE; a.K = 64;
        a.B = slot(15); a.ldb = 768; a.bias = b_pre;
        a.outb = pe1; a.ldo = 768;
        gemm_k<EPI_TANH><<<gE, blk, SMEM_BYTES>>>(a);
    }

    auto node_pass = [&](int slotBase, dim3 grid) {
        GArgs a = {};
        a.A = pxb; a.lda = 768; a.M = NN; a.K = 768;
        a.B = pWt; a.ldb = 768;
        a.outb = pP; a.ldo = PLD;
        a.multi = 1; a.slotBase = slotBase;
        gemm_k<EPI_STORE><<<grid, blk, SMEM_BYTES>>>(a);
    };
    auto edge_pass = [&](int epi, const __nv_bfloat16* eIn, int wslot, const float* bias,
                         int pdOff, int psOff, const __nv_bfloat16* aux, __nv_bfloat16* outb) {
        GArgs a = {};
        a.A = eIn; a.lda = 768; a.M = NE; a.K = 768;
        a.B = slot(wslot); a.ldb = 768; a.bias = bias;
        a.Pd = pP + pdOff; a.Ps = pP + psOff;
        a.dst = dst; a.srcI = src;
        a.aux = aux; a.outb = outb; a.ldo = 768; a.atom = px;
        if (epi == EPI_SIGF)      gemm_k<EPI_SIGF><<<gE, blk, SMEM_BYTES>>>(a);
        else if (epi == EPI_MSGS) gemm_k<EPI_MSGS><<<gE, blk, SMEM_BYTES>>>(a);
        else                      gemm_k<EPI_GATE><<<gE, blk, SMEM_BYTES>>>(a);
    };

    // 3. conv1 node projections: slots {0,1,3,4,6,7} -> P cols idx*768
    //    (P cols: 0 f_d, 768 f_s, 1536 s_d, 2304 s_s, 3072 e_d, 3840 e_s)
    node_pass(0, gN1);

    // 4. conv1 edge passes
    edge_pass(EPI_SIGF, pe1, 2, bf1, 0,    768,  nullptr, pSf);     // Sf = sigmoid(f)
    edge_pass(EPI_GATE, pe1, 8, be1, 3072, 3840, pe1,     pe2);     // e2 = e1*(1+sig(g))
    edge_pass(EPI_MSGS, pe1, 5, bs1, 1536, 2304, pSf,     nullptr); // x += scatter(relu(s)*Sf)

    // 5. refresh bf16 node features (x1)
    cvt_bf16_kernel<<<(NN * FF / 4 + 255) / 256, blk>>>(px, pxb, NN * FF / 4);

    // 6. conv2 node projections: slots {9,10,12,13}
    node_pass(9, gN2);

    // 7. conv2 edge passes (gate head unused by the reference -> skipped)
    edge_pass(EPI_SIGF, pe2, 11, bf2, 0,    768,  nullptr, pSf);
    edge_pass(EPI_MSGS, pe2, 14, bs2, 1536, 2304, pSf,     nullptr);

    // 8. pool + dense + softmax
    pool_kernel<<<dim3(3, 50), blk>>>();
    final_kernel<<<1, 32>>>(Wd, bd, (float*)d_out);
}